// round 1
// baseline (speedup 1.0000x reference)
#include <cuda_runtime.h>
#include <cuda_bf16.h>
#include <cstdint>

// NPSCalculator: nps = sum_{b,h,w} min_k sqrt( sum_c (x[b,c,h,w] - p[k,c] + 1e-6)^2 + 1e-6 ) / (B*C*H*W)
// B=8, C=3, H=512, W=512, NUM_COLORS=30.
// Strategy: sqrt(min) == min(sqrt) -> one sqrt per pixel; packed f32x2 math (2 pixels/instr)
// to double fp32 FMA throughput on sm_103a; printability staged in shared as (1e-6 - p)
// duplicated into both f32x2 lanes; warp-reduce + per-warp float atomicAdd.

#define HW_   262144           // 512*512
#define CHW_  (3*HW_)
#define NPIX_ 2097152          // 8*512*512
#define INV_SIZE_ (1.0f/6291456.0f)   // 1/(8*3*512*512)
#define THREADS_ 256
#define BLOCKS_  1024          // 262144 threads * 8 pixels = 2097152

typedef unsigned long long u64;

__device__ __forceinline__ u64 f2pk(float lo, float hi) {
    u64 r; asm("mov.b64 %0, {%1, %2};" : "=l"(r) : "f"(lo), "f"(hi)); return r;
}
__device__ __forceinline__ void f2unpk(u64 v, float& lo, float& hi) {
    asm("mov.b64 {%0, %1}, %2;" : "=f"(lo), "=f"(hi) : "l"(v));
}
__device__ __forceinline__ u64 add2(u64 a, u64 b) {
    u64 r; asm("add.rn.f32x2 %0, %1, %2;" : "=l"(r) : "l"(a), "l"(b)); return r;
}
__device__ __forceinline__ u64 fma2(u64 a, u64 b, u64 c) {
    u64 r; asm("fma.rn.f32x2 %0, %1, %2, %3;" : "=l"(r) : "l"(a), "l"(b), "l"(c)); return r;
}

__global__ void nps_zero_kernel(float* out) { out[0] = 0.0f; }

__global__ __launch_bounds__(THREADS_)
void nps_main_kernel(const float* __restrict__ adv,
                     const float* __restrict__ prn,
                     float* __restrict__ out)
{
    __shared__ u64 shNP[90];   // (1e-6 - p[k][c]) duplicated into both lanes
    int tid = threadIdx.x;
    if (tid < 90) {
        float v = 1e-6f - prn[tid];
        shNP[tid] = f2pk(v, v);
    }
    __syncthreads();

    // Two float4 pixel-groups per thread (8 pixels).
    int g0 = blockIdx.x * (2 * THREADS_) + tid;   // float4-group index
    int g1 = g0 + THREADS_;

    float4 a0, a1, a2, b0, b1, b2;
    {
        int p4 = g0 * 4;
        int b  = p4 >> 18;            // / HW_
        int hw = p4 & (HW_ - 1);
        const float4* q = reinterpret_cast<const float4*>(adv + (size_t)b * CHW_ + hw);
        a0 = q[0];
        a1 = q[HW_ / 4];
        a2 = q[2 * (HW_ / 4)];
    }
    {
        int p4 = g1 * 4;
        int b  = p4 >> 18;
        int hw = p4 & (HW_ - 1);
        const float4* q = reinterpret_cast<const float4*>(adv + (size_t)b * CHW_ + hw);
        b0 = q[0];
        b1 = q[HW_ / 4];
        b2 = q[2 * (HW_ / 4)];
    }

    // 4 pixel-pairs, each pair packed per channel.
    u64 XA0 = f2pk(a0.x, a0.y), XA1 = f2pk(a1.x, a1.y), XA2 = f2pk(a2.x, a2.y);
    u64 XB0 = f2pk(a0.z, a0.w), XB1 = f2pk(a1.z, a1.w), XB2 = f2pk(a2.z, a2.w);
    u64 XC0 = f2pk(b0.x, b0.y), XC1 = f2pk(b1.x, b1.y), XC2 = f2pk(b2.x, b2.y);
    u64 XD0 = f2pk(b0.z, b0.w), XD1 = f2pk(b1.z, b1.w), XD2 = f2pk(b2.z, b2.w);

    const u64 EPS2 = f2pk(1e-6f, 1e-6f);

    float mn0 = 1e30f, mn1 = 1e30f, mn2 = 1e30f, mn3 = 1e30f;
    float mn4 = 1e30f, mn5 = 1e30f, mn6 = 1e30f, mn7 = 1e30f;

    #pragma unroll 3
    for (int k = 0; k < 30; k++) {
        u64 p0 = shNP[k * 3 + 0];
        u64 p1 = shNP[k * 3 + 1];
        u64 p2 = shNP[k * 3 + 2];
        float lo, hi;
        u64 d, acc;

        d = add2(XA0, p0); acc = fma2(d, d, EPS2);
        d = add2(XA1, p1); acc = fma2(d, d, acc);
        d = add2(XA2, p2); acc = fma2(d, d, acc);
        f2unpk(acc, lo, hi); mn0 = fminf(mn0, lo); mn1 = fminf(mn1, hi);

        d = add2(XB0, p0); acc = fma2(d, d, EPS2);
        d = add2(XB1, p1); acc = fma2(d, d, acc);
        d = add2(XB2, p2); acc = fma2(d, d, acc);
        f2unpk(acc, lo, hi); mn2 = fminf(mn2, lo); mn3 = fminf(mn3, hi);

        d = add2(XC0, p0); acc = fma2(d, d, EPS2);
        d = add2(XC1, p1); acc = fma2(d, d, acc);
        d = add2(XC2, p2); acc = fma2(d, d, acc);
        f2unpk(acc, lo, hi); mn4 = fminf(mn4, lo); mn5 = fminf(mn5, hi);

        d = add2(XD0, p0); acc = fma2(d, d, EPS2);
        d = add2(XD1, p1); acc = fma2(d, d, acc);
        d = add2(XD2, p2); acc = fma2(d, d, acc);
        f2unpk(acc, lo, hi); mn6 = fminf(mn6, lo); mn7 = fminf(mn7, hi);
    }

    float s = sqrtf(mn0) + sqrtf(mn1) + sqrtf(mn2) + sqrtf(mn3)
            + sqrtf(mn4) + sqrtf(mn5) + sqrtf(mn6) + sqrtf(mn7);
    s *= INV_SIZE_;

    // warp reduction
    #pragma unroll
    for (int off = 16; off > 0; off >>= 1)
        s += __shfl_xor_sync(0xffffffffu, s, off);

    if ((tid & 31) == 0)
        atomicAdd(out, s);
}

extern "C" void kernel_launch(void* const* d_in, const int* in_sizes, int n_in,
                              void* d_out, int out_size)
{
    const float* adv = (const float*)d_in[0];   // (8,3,512,512) f32
    const float* prn = (const float*)d_in[1];   // (30,3) f32
    float* out = (float*)d_out;

    nps_zero_kernel<<<1, 1>>>(out);
    nps_main_kernel<<<BLOCKS_, THREADS_>>>(adv, prn, out);
}

// round 2
// speedup vs baseline: 1.1235x; 1.1235x over previous
#include <cuda_runtime.h>
#include <cuda_bf16.h>
#include <cstdint>

// NPSCalculator: nps = sum_{b,h,w} min_k sqrt( sum_c (x[b,c,h,w] - p[k,c] + 1e-6)^2 + 1e-6 ) / size
// B=8, C=3, H=512, W=512, NUM_COLORS=30.
//
// R2 strategy:
//  - dist^2 = ssq + acc_k where ssq = sum_c x_c^2 + 1e-6 (per-pixel constant) and
//    acc_k = sum_c (2 v_kc) x_c + sum_c v_kc^2, v = 1e-6 - p.  Inner loop = 3 fma2 per
//    color per pixel-pair (packed f32x2, 2 pixels/instr) -> half the fma work of R1.
//  - min_k sqrt(...) == sqrt(min_k ...), and ssq constant over k -> min over acc only.
//  - 512 blocks x 256 threads: single wave on 148 SMs even at 4 blocks/SM.
//  - single kernel launch: per-block partials + atomicInc last-block reduction
//    (counter wraps to 0 every launch -> graph-replay safe, no zero kernel).

#define HW_       262144
#define CHW_      (3 * HW_)
#define THREADS_  256
#define BLOCKS_   512
#define NTHREADS_ (THREADS_ * BLOCKS_)       // 131072
#define INV_SIZE_ (1.0f / 6291456.0f)

typedef unsigned long long u64;

__device__ float        g_partial[BLOCKS_];
__device__ unsigned int g_count = 0;

__device__ __forceinline__ u64 f2pk(float lo, float hi) {
    u64 r; asm("mov.b64 %0, {%1, %2};" : "=l"(r) : "f"(lo), "f"(hi)); return r;
}
__device__ __forceinline__ void f2unpk(u64 v, float& lo, float& hi) {
    asm("mov.b64 {%0, %1}, %2;" : "=f"(lo), "=f"(hi) : "l"(v));
}
__device__ __forceinline__ u64 fma2(u64 a, u64 b, u64 c) {
    u64 r; asm("fma.rn.f32x2 %0, %1, %2, %3;" : "=l"(r) : "l"(a), "l"(b), "l"(c)); return r;
}

__global__ __launch_bounds__(THREADS_)
void nps_kernel(const float* __restrict__ adv,
                const float* __restrict__ prn,
                float* __restrict__ out)
{
    // [k][0] = {W0, W1}, [k][1] = {W2, C};  W_c = 2*(1e-6 - p_kc) dup'd, C = sum v^2 dup'd
    __shared__ ulonglong2 shWC[60];
    __shared__ float      shRed[8];
    __shared__ int        shLast;

    int tid = threadIdx.x;
    if (tid < 30) {
        float v0 = 1e-6f - prn[tid * 3 + 0];
        float v1 = 1e-6f - prn[tid * 3 + 1];
        float v2 = 1e-6f - prn[tid * 3 + 2];
        float c  = v0 * v0 + v1 * v1 + v2 * v2;
        shWC[tid * 2 + 0] = make_ulonglong2(f2pk(2.f * v0, 2.f * v0),
                                            f2pk(2.f * v1, 2.f * v1));
        shWC[tid * 2 + 1] = make_ulonglong2(f2pk(2.f * v2, 2.f * v2),
                                            f2pk(c, c));
    }
    __syncthreads();

    const u64 EPS2 = f2pk(1e-6f, 1e-6f);
    int tglob = blockIdx.x * THREADS_ + tid;

    float tsum = 0.0f;

    #pragma unroll
    for (int chunk = 0; chunk < 2; chunk++) {
        // two float4-groups (8 pixels) per chunk, stride NTHREADS_ groups for coalescing
        int g0 = tglob + (2 * chunk) * NTHREADS_;
        int g1 = g0 + NTHREADS_;

        float4 a0, a1, a2, b0, b1, b2;
        {
            int p4 = g0 * 4;
            const float4* q = reinterpret_cast<const float4*>(
                adv + (size_t)(p4 >> 18) * CHW_ + (p4 & (HW_ - 1)));
            a0 = q[0]; a1 = q[HW_ / 4]; a2 = q[2 * (HW_ / 4)];
        }
        {
            int p4 = g1 * 4;
            const float4* q = reinterpret_cast<const float4*>(
                adv + (size_t)(p4 >> 18) * CHW_ + (p4 & (HW_ - 1)));
            b0 = q[0]; b1 = q[HW_ / 4]; b2 = q[2 * (HW_ / 4)];
        }

        // 4 pixel-pairs per chunk
        u64 XA0 = f2pk(a0.x, a0.y), XA1 = f2pk(a1.x, a1.y), XA2 = f2pk(a2.x, a2.y);
        u64 XB0 = f2pk(a0.z, a0.w), XB1 = f2pk(a1.z, a1.w), XB2 = f2pk(a2.z, a2.w);
        u64 XC0 = f2pk(b0.x, b0.y), XC1 = f2pk(b1.x, b1.y), XC2 = f2pk(b2.x, b2.y);
        u64 XD0 = f2pk(b0.z, b0.w), XD1 = f2pk(b1.z, b1.w), XD2 = f2pk(b2.z, b2.w);

        // per-pixel sum of squares + 1e-6 (packed)
        u64 sA = fma2(XA0, XA0, EPS2); sA = fma2(XA1, XA1, sA); sA = fma2(XA2, XA2, sA);
        u64 sB = fma2(XB0, XB0, EPS2); sB = fma2(XB1, XB1, sB); sB = fma2(XB2, XB2, sB);
        u64 sC = fma2(XC0, XC0, EPS2); sC = fma2(XC1, XC1, sC); sC = fma2(XC2, XC2, sC);
        u64 sD = fma2(XD0, XD0, EPS2); sD = fma2(XD1, XD1, sD); sD = fma2(XD2, XD2, sD);

        float mA0 = 1e30f, mA1 = 1e30f, mB0 = 1e30f, mB1 = 1e30f;
        float mC0 = 1e30f, mC1 = 1e30f, mD0 = 1e30f, mD1 = 1e30f;

        #pragma unroll 6
        for (int k = 0; k < 30; k++) {
            ulonglong2 w01 = shWC[k * 2 + 0];
            ulonglong2 w2c = shWC[k * 2 + 1];
            u64 w0 = w01.x, w1 = w01.y, w2 = w2c.x, ck = w2c.y;
            float lo, hi;
            u64 acc;

            acc = fma2(w0, XA0, ck); acc = fma2(w1, XA1, acc); acc = fma2(w2, XA2, acc);
            f2unpk(acc, lo, hi); mA0 = fminf(mA0, lo); mA1 = fminf(mA1, hi);

            acc = fma2(w0, XB0, ck); acc = fma2(w1, XB1, acc); acc = fma2(w2, XB2, acc);
            f2unpk(acc, lo, hi); mB0 = fminf(mB0, lo); mB1 = fminf(mB1, hi);

            acc = fma2(w0, XC0, ck); acc = fma2(w1, XC1, acc); acc = fma2(w2, XC2, acc);
            f2unpk(acc, lo, hi); mC0 = fminf(mC0, lo); mC1 = fminf(mC1, hi);

            acc = fma2(w0, XD0, ck); acc = fma2(w1, XD1, acc); acc = fma2(w2, XD2, acc);
            f2unpk(acc, lo, hi); mD0 = fminf(mD0, lo); mD1 = fminf(mD1, hi);
        }

        float sAl, sAh, sBl, sBh, sCl, sCh, sDl, sDh;
        f2unpk(sA, sAl, sAh); f2unpk(sB, sBl, sBh);
        f2unpk(sC, sCl, sCh); f2unpk(sD, sDl, sDh);

        tsum += sqrtf(mA0 + sAl) + sqrtf(mA1 + sAh)
              + sqrtf(mB0 + sBl) + sqrtf(mB1 + sBh)
              + sqrtf(mC0 + sCl) + sqrtf(mC1 + sCh)
              + sqrtf(mD0 + sDl) + sqrtf(mD1 + sDh);
    }

    // warp reduce
    #pragma unroll
    for (int off = 16; off > 0; off >>= 1)
        tsum += __shfl_xor_sync(0xffffffffu, tsum, off);
    if ((tid & 31) == 0) shRed[tid >> 5] = tsum;
    __syncthreads();

    // block reduce + publish partial, then last-block final reduction
    if (tid == 0) {
        float bs = shRed[0] + shRed[1] + shRed[2] + shRed[3]
                 + shRed[4] + shRed[5] + shRed[6] + shRed[7];
        g_partial[blockIdx.x] = bs;
        __threadfence();
        unsigned int prev = atomicInc(&g_count, BLOCKS_ - 1);
        shLast = (prev == BLOCKS_ - 1);
    }
    __syncthreads();

    if (shLast) {
        volatile float* vp = g_partial;
        float s = vp[tid] + vp[tid + THREADS_];
        #pragma unroll
        for (int off = 16; off > 0; off >>= 1)
            s += __shfl_xor_sync(0xffffffffu, s, off);
        if ((tid & 31) == 0) shRed[tid >> 5] = s;
        __syncthreads();
        if (tid == 0) {
            float tot = shRed[0] + shRed[1] + shRed[2] + shRed[3]
                      + shRed[4] + shRed[5] + shRed[6] + shRed[7];
            out[0] = tot * INV_SIZE_;
        }
    }
}

extern "C" void kernel_launch(void* const* d_in, const int* in_sizes, int n_in,
                              void* d_out, int out_size)
{
    const float* adv = (const float*)d_in[0];   // (8,3,512,512) f32
    const float* prn = (const float*)d_in[1];   // (30,3) f32
    nps_kernel<<<BLOCKS_, THREADS_>>>(adv, prn, (float*)d_out);
}